// round 17
// baseline (speedup 1.0000x reference)
#include <cuda_runtime.h>
#include <math.h>
#include <stdint.h>

#define B_SZ   256
#define T_SZ   64
#define IN_SZ  500
#define HID    512
#define G4     2048
#define RAWN   16532
#define NA     500
#define NF     32
#define GRIDN  256

__device__ float g_xg[(size_t)T_SZ * B_SZ * G4];
__device__ float g_hseq[(size_t)T_SZ * B_SZ * HID];
__device__ float g_hA[B_SZ * HID];
__device__ float g_hB[B_SZ * HID];
__device__ float g_raw[(size_t)B_SZ * RAWN];
__device__ unsigned long long g_flags[GRIDN];
__device__ uint32_t g_xc[(size_t)T_SZ * B_SZ * HID];
__device__ uint32_t g_wc0[(size_t)G4 * HID];
__device__ uint32_t g_wc1[(size_t)G4 * HID];
__device__ uint32_t g_wfc[(size_t)RAWN * HID];

__device__ __forceinline__ float sigmf(float x) { return 1.f / (1.f + expf(-x)); }

__device__ __forceinline__ uint32_t f2tf32(float f) {
    uint32_t r;
    asm("cvt.rna.tf32.f32 %0, %1;" : "=r"(r) : "f"(f));
    return r;
}

__device__ __forceinline__ void mma_tf32(float* c, const uint32_t* a, const uint32_t* b) {
    asm volatile(
        "mma.sync.aligned.m16n8k8.row.col.f32.tf32.tf32.f32 "
        "{%0,%1,%2,%3}, {%4,%5,%6,%7}, {%8,%9}, {%0,%1,%2,%3};\n"
        : "+f"(c[0]), "+f"(c[1]), "+f"(c[2]), "+f"(c[3])
        : "r"(a[0]), "r"(a[1]), "r"(a[2]), "r"(a[3]), "r"(b[0]), "r"(b[1]));
}

__device__ __forceinline__ void ldsm_x4(uint32_t* r, uint32_t addr) {
    asm volatile("ldmatrix.sync.aligned.m8n8.x4.shared.b16 {%0,%1,%2,%3}, [%4];"
        : "=r"(r[0]), "=r"(r[1]), "=r"(r[2]), "=r"(r[3]) : "r"(addr));
}

__device__ __forceinline__ uint32_t smem_u32(const void* p) {
    uint32_t a;
    asm("{ .reg .u64 t; cvta.to.shared.u64 t, %1; cvt.u32.u64 %0, t; }" : "=r"(a) : "l"(p));
    return a;
}

// ---------------- prep kernels (vectorized, R16 winners) ----------------
__global__ void cvt_pad_v4(const float* __restrict__ in, uint32_t* __restrict__ out,
                           int Nrows, int Kin)
{
    size_t idx = (size_t)blockIdx.x * 256 + threadIdx.x;
    if (idx >= (size_t)Nrows * 128) return;
    int n  = (int)(idx >> 7);
    int k4 = (int)(idx & 127) << 2;
    uint4 u = make_uint4(0u, 0u, 0u, 0u);
    if (k4 < Kin) {
        float4 v = *(const float4*)&in[(size_t)n * Kin + k4];
        u = make_uint4(f2tf32(v.x), f2tf32(v.y), f2tf32(v.z), f2tf32(v.w));
    }
    *(uint4*)&out[((size_t)n << 9) + k4] = u;
}

__global__ void cvt_x_v4(const float* __restrict__ x, uint32_t* __restrict__ out)
{
    size_t idx = (size_t)blockIdx.x * 256 + threadIdx.x;
    int r  = (int)(idx >> 7);
    int k4 = (int)(idx & 127) << 2;
    int t = r >> 8, b = r & 255;
    uint4 u = make_uint4(0u, 0u, 0u, 0u);
    if (k4 < IN_SZ) {
        float4 v = *(const float4*)&x[((size_t)b * T_SZ + t) * IN_SZ + k4];
        u = make_uint4(f2tf32(v.x), f2tf32(v.y), f2tf32(v.z), f2tf32(v.w));
    }
    *(uint4*)&out[((size_t)r << 9) + k4] = u;
}

// ================= persistent LSTM v2 (R14, unchanged) =================
#define W_STR    516
#define A_STR    68
#define OFF_A2   66048
#define WBUFS    8704
#define ABUF2    4352
#define OFF_XG2  100864
#define SM_BYTES2 109056

__global__ __launch_bounds__(128, 2) void lstm_persist(
    const float* __restrict__ w_hh, int layer)
{
    extern __shared__ __align__(16) uint32_t smraw[];
    uint32_t* Wsm = smraw;
    float*    smf = (float*)smraw;
    const uint32_t smem = smem_u32(smraw);

    const int tid  = threadIdx.x;
    const int lane = tid & 31;
    const int warp = tid >> 5;
    const int wm   = warp * 16;
    const int h0   = (blockIdx.x & 63) * 8;
    const int m0   = (blockIdx.x >> 6) * 64;

#pragma unroll
    for (int i = 0; i < 32; i++) {
        int s   = tid + (i << 7);
        int row = s >> 7;
        int kq  = s & 127;
        int wr  = ((row & 3) << 9) + h0 + (row >> 2);
        float4 v = *(const float4*)&w_hh[(size_t)wr * HID + (kq << 2)];
        *(uint4*)&Wsm[row * W_STR + (kq << 2)] =
            make_uint4(f2tf32(v.x), f2tf32(v.y), f2tf32(v.z), f2tf32(v.w));
    }

    const uint32_t warpA = smem + OFF_A2 + (uint32_t)warp * WBUFS;
    const uint32_t aFrag = warpA
        + (uint32_t)(((lane & 15) * A_STR + (lane >> 4) * 4) << 2);
    const uint32_t rB = (lane & 7) + ((lane & 16) ? 8 : 0);
    const uint32_t bBase0 = smem + (uint32_t)((rB * W_STR + ((lane >> 3) & 1) * 4) << 2);
    const uint32_t bBase1 = bBase0 + 16 * W_STR * 4;

    const uint32_t xgBase = smem + OFF_XG2 + (uint32_t)warp * 2048;
    const int xgW = (int)(OFF_XG2 / 4) + warp * 512;
    const int csW = (int)(OFF_A2 / 4) + warp * (WBUFS / 4);

    const unsigned long long barBase =
        *(volatile unsigned long long*)&g_flags[blockIdx.x];

    float creg[4] = {0.f, 0.f, 0.f, 0.f};

    __syncthreads();

    {
#pragma unroll
        for (int i = 0; i < 4; i++) {
            int idx = lane + 32 * i;
            int q = idx >> 5, r = (idx >> 1) & 15, gg = idx & 1;
            const float* src = g_xg + ((size_t)0 * B_SZ + m0 + wm + r) * G4
                             + q * HID + h0 + gg * 4;
            asm volatile("cp.async.cg.shared.global [%0], [%1], 16;"
                :: "r"(xgBase + (uint32_t)(q * 512 + r * 32 + gg * 16)), "l"(src));
        }
        asm volatile("cp.async.commit_group;" ::: "memory");
    }

#define STAGE_H(c)                                                              \
    {                                                                           \
        uint32_t dbuf = warpA + (uint32_t)(((c) & 1) * ABUF2);                  \
        _Pragma("unroll")                                                       \
        for (int i = 0; i < 8; i++) {                                           \
            int idx = lane + 32 * i;                                            \
            int rl = idx >> 4;                                                  \
            int gr = idx & 15;                                                  \
            const float* src = h_in + (size_t)(m0 + wm + rl) * HID              \
                             + (c) * 64 + gr * 4;                               \
            asm volatile("cp.async.cg.shared.global [%0], [%1], 16;"            \
                :: "r"(dbuf + (uint32_t)(rl * 272 + gr * 16)), "l"(src));       \
        }                                                                       \
        asm volatile("cp.async.commit_group;" ::: "memory");                    \
    }

#define MMA_CHUNK(ck)                                                           \
    {                                                                           \
        const uint32_t ab  = aFrag  + (uint32_t)(((ck) & 1) * ABUF2);           \
        const uint32_t wb0 = bBase0 + (uint32_t)((ck) * 256);                   \
        const uint32_t wb1 = bBase1 + (uint32_t)((ck) * 256);                   \
        _Pragma("unroll")                                                       \
        for (int k8 = 0; k8 < 8; k8++) {                                        \
            uint32_t a[4], b0[4], b1[4];                                        \
            ldsm_x4(a,  ab  + (uint32_t)(k8 * 32));                             \
            ldsm_x4(b0, wb0 + (uint32_t)(k8 * 32));                             \
            ldsm_x4(b1, wb1 + (uint32_t)(k8 * 32));                             \
            mma_tf32(c[0], a, b0);                                              \
            mma_tf32(c[1], a, b0 + 2);                                          \
            mma_tf32(c[2], a, b1);                                              \
            mma_tf32(c[3], a, b1 + 2);                                          \
        }                                                                       \
    }

    for (int t = 0; t < T_SZ; t++) {
        const float* h_in = (t & 1) ? g_hB : g_hA;
        float* h_out      = (t & 1) ? g_hA : g_hB;

        float c[4][4];
#pragma unroll
        for (int nt = 0; nt < 4; nt++)
#pragma unroll
            for (int q = 0; q < 4; q++) c[nt][q] = 0.f;

        if (t > 0) {
            STAGE_H(0) STAGE_H(1)
#define ITER(ck, WN)                                                            \
            asm volatile("cp.async.wait_group " #WN ";" ::: "memory");          \
            MMA_CHUNK(ck)                                                       \
            if ((ck) < 6) STAGE_H((ck) + 2)
            ITER(0, 1) ITER(1, 1) ITER(2, 1) ITER(3, 1)
            ITER(4, 1) ITER(5, 1) ITER(6, 1) ITER(7, 0)
#undef ITER
            {
                const int gid = lane >> 2, tig = lane & 3;
#pragma unroll
                for (int nt = 0; nt < 4; nt++) {
                    int cb = nt * 8 + 2 * tig;
                    smf[csW + gid * 36 + cb]           = c[nt][0];
                    smf[csW + gid * 36 + cb + 1]       = c[nt][1];
                    smf[csW + (gid + 8) * 36 + cb]     = c[nt][2];
                    smf[csW + (gid + 8) * 36 + cb + 1] = c[nt][3];
                }
            }
        } else {
            asm volatile("cp.async.wait_group 0;" ::: "memory");
        }
        __syncwarp();

        {
            const int rl = lane >> 1;
            const int hq = lane & 1;
            float4 gv[4];
            if (t > 0) {
#pragma unroll
                for (int k = 0; k < 4; k++)
                    gv[k] = *(float4*)&smf[csW + rl * 36 + hq * 16 + 4 * k];
            } else {
#pragma unroll
                for (int k = 0; k < 4; k++) gv[k] = make_float4(0, 0, 0, 0);
            }
            float4 xq[4];
#pragma unroll
            for (int q = 0; q < 4; q++)
                xq[q] = *(float4*)&smf[xgW + q * 128 + rl * 8 + hq * 4];

            float xiv[4] = {xq[0].x, xq[0].y, xq[0].z, xq[0].w};
            float xfv[4] = {xq[1].x, xq[1].y, xq[1].z, xq[1].w};
            float xgv[4] = {xq[2].x, xq[2].y, xq[2].z, xq[2].w};
            float xov[4] = {xq[3].x, xq[3].y, xq[3].z, xq[3].w};

            uint32_t hb[4];
#pragma unroll
            for (int k = 0; k < 4; k++) {
                float gi = gv[k].x + xiv[k];
                float gf = gv[k].y + xfv[k];
                float gg = gv[k].z + xgv[k];
                float go = gv[k].w + xov[k];
                float cn = sigmf(gf) * creg[k] + sigmf(gi) * tanhf(gg);
                float hn = sigmf(go) * tanhf(cn);
                creg[k] = cn;
                hb[k] = f2tf32(hn);
            }
            const int b = m0 + wm + rl;
            const int hh = h0 + hq * 4;
            *(uint4*)&h_out[(size_t)b * HID + hh] = make_uint4(hb[0], hb[1], hb[2], hb[3]);
            if (layer == 0)
                *(uint4*)&g_hseq[((size_t)t * B_SZ + b) * HID + hh] =
                    make_uint4(hb[0], hb[1], hb[2], hb[3]);
        }

        if (t + 1 < T_SZ) {
#pragma unroll
            for (int i = 0; i < 4; i++) {
                int idx = lane + 32 * i;
                int q = idx >> 5, r = (idx >> 1) & 15, gg = idx & 1;
                const float* src = g_xg + ((size_t)(t + 1) * B_SZ + m0 + wm + r) * G4
                                 + q * HID + h0 + gg * 4;
                asm volatile("cp.async.cg.shared.global [%0], [%1], 16;"
                    :: "r"(xgBase + (uint32_t)(q * 512 + r * 32 + gg * 16)), "l"(src));
            }
            asm volatile("cp.async.commit_group;" ::: "memory");

            __syncthreads();
            const unsigned long long tgt = barBase + (unsigned long long)(t + 1);
            if (tid == 0)
                asm volatile("st.release.gpu.global.u64 [%0], %1;"
                             :: "l"(&g_flags[blockIdx.x]), "l"(tgt) : "memory");
            {
                unsigned long long v;
                do {
                    asm volatile("ld.acquire.gpu.global.u64 %0, [%1];"
                                 : "=l"(v) : "l"(&g_flags[tid]) : "memory");
                } while (v < tgt);
                do {
                    asm volatile("ld.acquire.gpu.global.u64 %0, [%1];"
                                 : "=l"(v) : "l"(&g_flags[tid + 128]) : "memory");
                } while (v < tgt);
            }
            __syncthreads();
        }
    }
#undef STAGE_H
#undef MMA_CHUNK
}

// ============ GEMM v5 (R15 winner, unchanged) ============
#define GP_ST   36
#define GP_BUF  18432
#define GP_BOFF 55296
#define GP_CST  132
#define GP_SM   110592

__global__ __launch_bounds__(128, 2) void gemm_cp(
    const uint32_t* __restrict__ A,
    const uint32_t* __restrict__ W,
    const float* __restrict__ bias1, const float* __restrict__ bias2,
    float* __restrict__ C, int N)
{
    extern __shared__ __align__(16) uint32_t gsm[];
    float* Cs = (float*)gsm;
    const uint32_t smem = smem_u32(gsm);

    const int tid  = threadIdx.x;
    const int lane = tid & 31;
    const int warp = tid >> 5;
    const int wm   = (warp >> 1) * 64;
    const int wn   = (warp & 1) * 64;
    const int m0   = blockIdx.y * 128;
    const int n0   = blockIdx.x * 128;

    float c[4][8][4];
#pragma unroll
    for (int mt = 0; mt < 4; mt++)
#pragma unroll
        for (int nt = 0; nt < 8; nt++)
#pragma unroll
            for (int q = 0; q < 4; q++) c[mt][nt][q] = 0.f;

    const uint32_t aOff = (uint32_t)(((wm + (lane & 15)) * GP_ST + (lane >> 4) * 4) << 2);
    const uint32_t bRow = wn + (lane & 7) + ((lane & 16) ? 8 : 0);
    const uint32_t bOff = (uint32_t)((bRow * GP_ST + ((lane >> 3) & 1) * 4) << 2);

#define LOADST(kt)                                                               \
    {                                                                            \
        const uint32_t abase = smem + (uint32_t)(((kt) % 3) * GP_BUF);           \
        const uint32_t bbase = smem + (uint32_t)(GP_BOFF + ((kt) % 3) * GP_BUF); \
        _Pragma("unroll")                                                        \
        for (int i = 0; i < 8; i++) {                                            \
            int idx = tid + (i << 7);                                            \
            int row = idx >> 3, kq = idx & 7;                                    \
            const uint32_t* srcA = A + (size_t)(m0 + row) * 512 + (kt) * 32 + kq * 4; \
            asm volatile("cp.async.cg.shared.global [%0], [%1], 16;"             \
                :: "r"(abase + (uint32_t)((row * GP_ST + kq * 4) << 2)), "l"(srcA)); \
            int wr = n0 + row; if (wr >= N) wr = N - 1;                          \
            const uint32_t* srcB = W + (size_t)wr * 512 + (kt) * 32 + kq * 4;    \
            asm volatile("cp.async.cg.shared.global [%0], [%1], 16;"             \
                :: "r"(bbase + (uint32_t)((row * GP_ST + kq * 4) << 2)), "l"(srcB)); \
        }                                                                        \
        asm volatile("cp.async.commit_group;" ::: "memory");                     \
    }

#define GMMA(kt)                                                                 \
    {                                                                            \
        const uint32_t abuf = smem + (uint32_t)(((kt) % 3) * GP_BUF);            \
        const uint32_t bbuf = smem + (uint32_t)(GP_BOFF + ((kt) % 3) * GP_BUF);  \
        _Pragma("unroll")                                                        \
        for (int k8 = 0; k8 < 4; k8++) {                                         \
            uint32_t fa[4][4], fb[4][4];                                         \
            _Pragma("unroll")                                                    \
            for (int mt = 0; mt < 4; mt++)                                       \
                ldsm_x4(fa[mt], abuf + aOff                                      \
                        + (uint32_t)(mt * 16 * GP_ST * 4 + k8 * 32));            \
            _Pragma("unroll")                                                    \
            for (int n4 = 0; n4 < 4; n4++)                                       \
                ldsm_x4(fb[n4], bbuf + bOff                                      \
                        + (uint32_t)(n4 * 16 * GP_ST * 4 + k8 * 32));            \
            _Pragma("unroll")                                                    \
            for (int mt = 0; mt < 4; mt++)                                       \
                _Pragma("unroll")                                                \
                for (int n4 = 0; n4 < 4; n4++) {                                 \
                    mma_tf32(c[mt][2 * n4],     fa[mt], fb[n4]);                 \
                    mma_tf32(c[mt][2 * n4 + 1], fa[mt], fb[n4] + 2);             \
                }                                                                \
        }                                                                        \
    }

#define GITER(kt, WN)                                                            \
    asm volatile("cp.async.wait_group " #WN ";" ::: "memory");                   \
    __syncthreads();                                                             \
    if ((kt) + 2 < 16) LOADST((kt) + 2)                                          \
    GMMA(kt)

    LOADST(0) LOADST(1)
    GITER(0, 1)  GITER(1, 1)  GITER(2, 1)  GITER(3, 1)
    GITER(4, 1)  GITER(5, 1)  GITER(6, 1)  GITER(7, 1)
    GITER(8, 1)  GITER(9, 1)  GITER(10, 1) GITER(11, 1)
    GITER(12, 1) GITER(13, 1) GITER(14, 1) GITER(15, 0)
#undef GITER
#undef GMMA
#undef LOADST

    __syncthreads();
    {
        const int gid = lane >> 2, tig = lane & 3;
#pragma unroll
        for (int mt = 0; mt < 4; mt++)
#pragma unroll
            for (int nt = 0; nt < 8; nt++) {
                int r  = wm + mt * 16 + gid;
                int cb = wn + nt * 8 + 2 * tig;
                Cs[r * GP_CST + cb]           = c[mt][nt][0];
                Cs[r * GP_CST + cb + 1]       = c[mt][nt][1];
                Cs[(r + 8) * GP_CST + cb]     = c[mt][nt][2];
                Cs[(r + 8) * GP_CST + cb + 1] = c[mt][nt][3];
            }
    }
    __syncthreads();

#pragma unroll
    for (int i = 0; i < 32; i++) {
        int idx = tid + (i << 7);
        int row = idx >> 5, cq = idx & 31;
        int colb = n0 + cq * 4;
        if (colb < N) {
            float4 v = *(float4*)&Cs[row * GP_CST + cq * 4];
            float4 b1 = *(const float4*)&bias1[colb];
            v.x += b1.x; v.y += b1.y; v.z += b1.z; v.w += b1.w;
            if (bias2) {
                float4 b2 = *(const float4*)&bias2[colb];
                v.x += b2.x; v.y += b2.y; v.z += b2.z; v.w += b2.w;
            }
            *(float4*)&C[(size_t)(m0 + row) * N + colb] = v;
        }
    }
}

// ---------------- Sigma (symmetric, R13 winner, unchanged) ----------------
__global__ __launch_bounds__(256) void sigma_sym(float* __restrict__ out)
{
    __shared__ float fvs[32];
    __shared__ float Ln[32][64];
    __shared__ float Lm[32][64];
    __shared__ float Ts[64][65];

    const int b = blockIdx.y;
    int L = blockIdx.x, bi = 0;
    while (L >= 8 - bi) { L -= 8 - bi; bi++; }
    const int bj = bi + L;
    const int m0 = bi * 64;
    const int n0 = bj * 64;

    const int tid = threadIdx.x;
    const int tx = tid & 15;
    const int ty = tid >> 4;
    const float* rb = g_raw + (size_t)b * RAWN;

    if (tid < 32) fvs[tid] = expf(rb[NA * NF + tid]);
    __syncthreads();

#pragma unroll
    for (int i = 0; i < 8; i++) {
        int idx = tid + i * 256;
        int nl = idx >> 5, f = idx & 31;
        int n = n0 + nl;
        float v = (n < NA) ? rb[n * NF + f] : 0.f;
        Ln[f][nl] = v * fvs[f];
        int m = m0 + nl;
        float w = (m < NA) ? rb[m * NF + f] : 0.f;
        Lm[f][nl] = w;
    }
    __syncthreads();

    float acc[4][4];
#pragma unroll
    for (int r = 0; r < 4; r++)
#pragma unroll
        for (int cc = 0; cc < 4; cc++) acc[r][cc] = 0.f;

#pragma unroll
    for (int f = 0; f < 32; f++) {
        float4 a  = *reinterpret_cast<const float4*>(&Ln[f][ty * 4]);
        float4 bb = *reinterpret_cast<const float4*>(&Lm[f][tx * 4]);
        float av[4] = {a.x, a.y, a.z, a.w};
        float bv[4] = {bb.x, bb.y, bb.z, bb.w};
#pragma unroll
        for (int r = 0; r < 4; r++)
#pragma unroll
            for (int cc = 0; cc < 4; cc++)
                acc[r][cc] = fmaf(av[r], bv[cc], acc[r][cc]);
    }

    const int mBase = m0 + tx * 4;
#pragma unroll
    for (int r = 0; r < 4; r++) {
        int nl = ty * 4 + r;
        int n = n0 + nl;
        float o[4] = {acc[r][0], acc[r][1], acc[r][2], acc[r][3]};
        Ts[nl][tx * 4]     = o[0];
        Ts[nl][tx * 4 + 1] = o[1];
        Ts[nl][tx * 4 + 2] = o[2];
        Ts[nl][tx * 4 + 3] = o[3];
        if (n < NA && mBase < NA) {
            int d = n - mBase;
            if (d >= 0 && d < 4) o[d] += expf(rb[NA * NF + NF + n]);
            float4 ov = {o[0], o[1], o[2], o[3]};
            *reinterpret_cast<float4*>(&out[(size_t)b * NA * NA + (size_t)n * NA + mBase]) = ov;
        }
    }

    if (bi != bj) {
        __syncthreads();
        for (int idx = tid; idx < 64 * 64; idx += 256) {
            int mr = idx >> 6;
            int nc = idx & 63;
            int m = m0 + mr;
            int ncol = n0 + nc;
            if (m < NA && ncol < NA)
                out[(size_t)b * NA * NA + (size_t)m * NA + ncol] = Ts[nc][mr];
        }
    }
}

// ---------------- launch ----------------
extern "C" void kernel_launch(void* const* d_in, const int* in_sizes, int n_in,
                              void* d_out, int out_size)
{
    const float* x     = (const float*)d_in[0];
    const float* w_ih0 = (const float*)d_in[1];
    const float* w_hh0 = (const float*)d_in[2];
    const float* b_ih0 = (const float*)d_in[3];
    const float* b_hh0 = (const float*)d_in[4];
    const float* w_ih1 = (const float*)d_in[5];
    const float* w_hh1 = (const float*)d_in[6];
    const float* b_ih1 = (const float*)d_in[7];
    const float* b_hh1 = (const float*)d_in[8];
    const float* fc_w  = (const float*)d_in[9];
    const float* fc_b  = (const float*)d_in[10];
    float* out = (float*)d_out;

    static bool init_done = false;
    static cudaStream_t s2;
    static cudaEvent_t evFork, evW1, evWfc;
    if (!init_done) {
        cudaFuncSetAttribute(lstm_persist,
            cudaFuncAttributeMaxDynamicSharedMemorySize, SM_BYTES2);
        cudaFuncSetAttribute(gemm_cp,
            cudaFuncAttributeMaxDynamicSharedMemorySize, GP_SM);
        cudaStreamCreateWithFlags(&s2, cudaStreamNonBlocking);
        cudaEventCreateWithFlags(&evFork, cudaEventDisableTiming);
        cudaEventCreateWithFlags(&evW1,   cudaEventDisableTiming);
        cudaEventCreateWithFlags(&evWfc,  cudaEventDisableTiming);
        init_done = true;
    }

    uint32_t *p_xc, *p_wc0, *p_wc1, *p_wfc;
    cudaGetSymbolAddress((void**)&p_xc,  g_xc);
    cudaGetSymbolAddress((void**)&p_wc0, g_wc0);
    cudaGetSymbolAddress((void**)&p_wc1, g_wc1);
    cudaGetSymbolAddress((void**)&p_wfc, g_wfc);
    float *p_xg, *p_hseq, *p_hA, *p_raw;
    cudaGetSymbolAddress((void**)&p_xg,   g_xg);
    cudaGetSymbolAddress((void**)&p_hseq, g_hseq);
    cudaGetSymbolAddress((void**)&p_hA,   g_hA);
    cudaGetSymbolAddress((void**)&p_raw,  g_raw);

    // ---- fork side stream for the late-consumed converts ----
    cudaEventRecord(evFork, 0);
    cudaStreamWaitEvent(s2, evFork, 0);
    cvt_pad_v4<<<(G4 * 128) / 256, 256, 0, s2>>>(w_ih1, p_wc1, G4, HID);
    cudaEventRecord(evW1, s2);
    cvt_pad_v4<<<((RAWN * 128) + 255) / 256, 256, 0, s2>>>(fc_w, p_wfc, RAWN, HID);
    cudaEventRecord(evWfc, s2);

    // ---- critical-path prep ----
    cvt_x_v4<<<(T_SZ * B_SZ * 128) / 256, 256>>>(x, p_xc);
    cvt_pad_v4<<<(G4 * 128) / 256, 256>>>(w_ih0, p_wc0, G4, IN_SZ);

    // ---- layer 0 ----
    gemm_cp<<<dim3(G4 / 128, (B_SZ * T_SZ) / 128), 128, GP_SM>>>(
        p_xc, p_wc0, b_ih0, b_hh0, p_xg, G4);
    lstm_persist<<<GRIDN, 128, SM_BYTES2>>>(w_hh0, 0);

    // ---- layer 1 (join w1 convert) ----
    cudaStreamWaitEvent(0, evW1, 0);
    gemm_cp<<<dim3(G4 / 128, (B_SZ * T_SZ) / 128), 128, GP_SM>>>(
        (const uint32_t*)p_hseq, p_wc1, b_ih1, b_hh1, p_xg, G4);
    lstm_persist<<<GRIDN, 128, SM_BYTES2>>>(w_hh1, 1);
    // final h (t=63, odd) in g_hA

    // ---- FC (join wfc convert) ----
    cudaStreamWaitEvent(0, evWfc, 0);
    gemm_cp<<<dim3((RAWN + 127) / 128, B_SZ / 128), 128, GP_SM>>>(
        (const uint32_t*)p_hA, p_wfc, fc_b, nullptr, p_raw, RAWN);

    // ---- Sigma (symmetric) ----
    sigma_sym<<<dim3(36, B_SZ), 256>>>(out);
}